// round 15
// baseline (speedup 1.0000x reference)
#include <cuda_runtime.h>
#include <cuda_fp16.h>
#include <math.h>
#include <stdint.h>

#define NTOK 16384
#define DIM  2048
#define HID  256
#define NEXP 5
#define RANK 16
#define NLOW 80
#define NCP  384
#define LSP  96
#define SCALING 2.0f
#define TIE_THRESH 0.005f

#define AST  40

// ---------------- static scratch ----------------
__device__ __half g_Xh[(size_t)NTOK * DIM];
__device__ __half g_Wcat[(size_t)DIM * NCP];
__device__ __half g_Bh[(size_t)LSP * DIM];
__device__ float  g_P[(size_t)NTOK * NCP];
__device__ __half g_LS[(size_t)NTOK * LSP];
__device__ int    g_nflag;
__device__ int    g_flags[NTOK];
__device__ float  g_Hp[(size_t)NTOK * 8 * 256];   // split-K partial hidden sums

// ---------------- PTX helpers ----------------
__device__ __forceinline__ uint32_t smem_u32(const void* p) {
    uint32_t a;
    asm("{ .reg .u64 t; cvta.to.shared.u64 t, %1; cvt.u32.u64 %0, t; }" : "=r"(a) : "l"(p));
    return a;
}
#define CP_ASYNC16(sm, gm) \
    asm volatile("cp.async.cg.shared.global [%0], [%1], 16;" :: "r"((uint32_t)(sm)), "l"(gm))
#define CP_COMMIT() asm volatile("cp.async.commit_group;" ::: "memory")
#define CP_WAIT(n)  asm volatile("cp.async.wait_group %0;" :: "n"(n) : "memory")

__device__ __forceinline__ void ldmA(uint32_t* a, uint32_t addr) {
    asm volatile("ldmatrix.sync.aligned.m8n8.x4.shared.b16 {%0,%1,%2,%3}, [%4];"
        : "=r"(a[0]), "=r"(a[1]), "=r"(a[2]), "=r"(a[3]) : "r"(addr));
}
__device__ __forceinline__ void ldmBT(uint32_t* b, uint32_t addr) {
    asm volatile("ldmatrix.sync.aligned.m8n8.x2.trans.shared.b16 {%0,%1}, [%2];"
        : "=r"(b[0]), "=r"(b[1]) : "r"(addr));
}
__device__ __forceinline__ void mma16816(float* c, const uint32_t* a, const uint32_t* b) {
    asm volatile("mma.sync.aligned.m16n8k16.row.col.f32.f16.f16.f32 "
        "{%0,%1,%2,%3}, {%4,%5,%6,%7}, {%8,%9}, {%0,%1,%2,%3};"
        : "+f"(c[0]), "+f"(c[1]), "+f"(c[2]), "+f"(c[3])
        : "r"(a[0]), "r"(a[1]), "r"(a[2]), "r"(a[3]), "r"(b[0]), "r"(b[1]));
}

// ---------------------------------------------------------------------------
// k0_all: fused prep.
// ---------------------------------------------------------------------------
__global__ void k0_all(const float* __restrict__ x,
                       const float* __restrict__ W1,
                       const float* __restrict__ A,
                       const float* __restrict__ B)
{
    const int b = blockIdx.x, tid = threadIdx.x;
    if (b < 16384) {
        size_t i = ((size_t)b * 256 + tid) * 8;
        float4 a = __ldg((const float4*)(x + i));
        float4 c = __ldg((const float4*)(x + i + 4));
        __half2 h0 = __float22half2_rn(make_float2(a.x, a.y));
        __half2 h1 = __float22half2_rn(make_float2(a.z, a.w));
        __half2 h2 = __float22half2_rn(make_float2(c.x, c.y));
        __half2 h3 = __float22half2_rn(make_float2(c.z, c.w));
        *(uint4*)(g_Xh + i) = make_uint4(*(uint32_t*)&h0, *(uint32_t*)&h1,
                                         *(uint32_t*)&h2, *(uint32_t*)&h3);
        if (b == 0 && tid == 0) g_nflag = 0;
    } else if (b < 16384 + 2048) {
        int k = b - 16384;
#pragma unroll
        for (int q = 0; q < 2; q++) {
            int n = tid + q * 256;
            if (n < NCP) {
                float v = 0.0f;
                if (n < HID) v = W1[(size_t)k * HID + n];
                else if (n < HID + NLOW) {
                    int c = n - HID;
                    v = A[((size_t)(c >> 4) * DIM + k) * RANK + (c & 15)];
                }
                g_Wcat[(size_t)k * NCP + n] = __float2half(v);
            }
        }
    } else {
        int j = b - 16384 - 2048;
        for (int d = tid; d < DIM; d += 256) {
            float v = (j < NLOW) ? B[(size_t)j * DIM + d] : 0.0f;
            g_Bh[(size_t)j * DIM + d] = __float2half(v);
        }
    }
}

// ---------------------------------------------------------------------------
// k1: P = x @ Wcat  via fp16 mma.sync.  BM=128 BN=128 BK=32, 8 warps,
// 3-stage cp.async pipeline, conflict-free A tiles (stride 40 halves).
// ---------------------------------------------------------------------------
#define K1_ATILE (128 * AST)
#define K1_BTILE (32 * 136)
__global__ void __launch_bounds__(256, 2) k1_mma() {
    __shared__ alignas(16) __half As[3][K1_ATILE];
    __shared__ alignas(16) __half Bs[3][K1_BTILE];

    const int tid = threadIdx.x, lane = tid & 31, warp = tid >> 5;
    const int m0 = (warp & 1) * 64, n0 = (warp >> 1) * 32;
    const int row0 = blockIdx.y * 128, col0 = blockIdx.x * 128;

    const uint32_t asb = smem_u32(&As[0][0]);
    const uint32_t bsb = smem_u32(&Bs[0][0]);

    float acc[4][4][4];
#pragma unroll
    for (int mi = 0; mi < 4; mi++)
#pragma unroll
        for (int ni = 0; ni < 4; ni++)
#pragma unroll
            for (int q = 0; q < 4; q++) acc[mi][ni][q] = 0.0f;

    const __half* xp = g_Xh + (size_t)row0 * DIM;
    const __half* wp = g_Wcat + col0;

#define LOAD_STAGE(S, K0) do {                                                   \
    uint32_t ab = asb + (uint32_t)(S) * (K1_ATILE * 2);                          \
    uint32_t bb = bsb + (uint32_t)(S) * (K1_BTILE * 2);                          \
    _Pragma("unroll")                                                            \
    for (int q = 0; q < 2; q++) {                                                \
        int idx = tid + q * 256;                                                 \
        int r = idx >> 2, c = idx & 3;                                           \
        CP_ASYNC16(ab + (uint32_t)(r * (AST * 2) + c * 16),                      \
                   xp + (size_t)r * DIM + (K0) + c * 8);                         \
    }                                                                            \
    _Pragma("unroll")                                                            \
    for (int q = 0; q < 2; q++) {                                                \
        int idx = tid + q * 256;                                                 \
        int kr = idx >> 4, c = idx & 15;                                         \
        CP_ASYNC16(bb + (uint32_t)(kr * 272 + c * 16),                           \
                   wp + (size_t)((K0) + kr) * NCP + c * 8);                      \
    }                                                                            \
} while (0)

    LOAD_STAGE(0, 0);  CP_COMMIT();
    LOAD_STAGE(1, 32); CP_COMMIT();

    int s = 0;
    for (int i = 0; i < 64; i++) {
        CP_WAIT(1);
        __syncthreads();
        if (i + 2 < 64) {
            int sn = s + 2; if (sn >= 3) sn -= 3;
            LOAD_STAGE(sn, (i + 2) * 32);
            CP_COMMIT();
        } else {
            CP_COMMIT();
        }
        uint32_t ab = asb + (uint32_t)s * (K1_ATILE * 2);
        uint32_t bb = bsb + (uint32_t)s * (K1_BTILE * 2);
#pragma unroll
        for (int kk = 0; kk < 2; kk++) {
            uint32_t a[4][4], b[4][2];
#pragma unroll
            for (int mi = 0; mi < 4; mi++)
                ldmA(a[mi], ab + (uint32_t)((m0 + mi * 16 + (lane & 15)) * (AST * 2) +
                                            (kk * 16 + (lane >> 4) * 8) * 2));
#pragma unroll
            for (int ni = 0; ni < 4; ni++)
                ldmBT(b[ni], bb + (uint32_t)((kk * 16 + (lane & 15)) * 272 +
                                             (n0 + ni * 8) * 2));
#pragma unroll
            for (int mi = 0; mi < 4; mi++)
#pragma unroll
                for (int ni = 0; ni < 4; ni++)
                    mma16816(acc[mi][ni], a[mi], b[ni]);
        }
        if (++s >= 3) s = 0;
    }
#undef LOAD_STAGE

#pragma unroll
    for (int mi = 0; mi < 4; mi++) {
        int r = row0 + m0 + mi * 16 + (lane >> 2);
#pragma unroll
        for (int ni = 0; ni < 4; ni++) {
            int c = col0 + n0 + ni * 8 + (lane & 3) * 2;
            *(float2*)&g_P[(size_t)r * NCP + c]       = make_float2(acc[mi][ni][0], acc[mi][ni][1]);
            *(float2*)&g_P[(size_t)(r + 8) * NCP + c] = make_float2(acc[mi][ni][2], acc[mi][ni][3]);
        }
    }
}

// ---------------------------------------------------------------------------
// k2: router — MLP rebuild. W2^T + b1 staged in smem; per-lane 8 contiguous
// hidden values via 2 LDG.128 (chain depth 2). Flags near-tie tokens.
// ---------------------------------------------------------------------------
__global__ void __launch_bounds__(256) k2_router(
    const float* __restrict__ b1,
    const float* __restrict__ W2,
    const float* __restrict__ b2)
{
    __shared__ float W2s[NEXP][260];     // transposed: W2s[e][h]
    __shared__ float b1s[256];

    const int tid = threadIdx.x, warp = tid >> 5, lane = tid & 31;

    for (int i = tid; i < HID * NEXP; i += 256) {
        int h = i / NEXP, e = i - h * NEXP;
        W2s[e][h] = W2[i];
    }
    b1s[tid] = b1[tid];
    __syncthreads();

    const int n = blockIdx.x * 8 + warp;
    const float* Pn = g_P + (size_t)n * NCP;

    // lane owns hidden cols lane*8 .. +7 (two independent LDG.128)
    float4 p0 = *(const float4*)(Pn + lane * 8);
    float4 p1 = *(const float4*)(Pn + lane * 8 + 4);
    float hv[8] = {p0.x, p0.y, p0.z, p0.w, p1.x, p1.y, p1.z, p1.w};
    float sv[8];
#pragma unroll
    for (int j = 0; j < 8; j++) {
        float v = hv[j] + b1s[lane * 8 + j];
        sv[j] = v / (1.0f + expf(-v));
    }

    float acc[NEXP];
#pragma unroll
    for (int e = 0; e < NEXP; e++) acc[e] = 0.0f;
#pragma unroll
    for (int j = 0; j < 8; j++) {
        int h = lane * 8 + j;
#pragma unroll
        for (int e = 0; e < NEXP; e++)
            acc[e] = fmaf(sv[j], W2s[e][h], acc[e]);
    }
#pragma unroll
    for (int e = 0; e < NEXP; e++)
#pragma unroll
        for (int off = 16; off > 0; off >>= 1)
            acc[e] += __shfl_down_sync(0xffffffffu, acc[e], off);

    int e0 = 0, e1 = 0;
    float w0 = 0.0f, w1 = 0.0f;
    if (lane == 0) {
        float lg[NEXP];
#pragma unroll
        for (int e = 0; e < NEXP; e++) lg[e] = acc[e] + b2[e];
        float l0 = lg[0]; e0 = 0;
#pragma unroll
        for (int e = 1; e < NEXP; e++) if (lg[e] > l0) { l0 = lg[e]; e0 = e; }
        float l1 = -3.402823466e38f; e1 = -1;
#pragma unroll
        for (int e = 0; e < NEXP; e++) if (e != e0 && lg[e] > l1) { l1 = lg[e]; e1 = e; }
        float l2 = -3.402823466e38f;
#pragma unroll
        for (int e = 0; e < NEXP; e++) if (e != e0 && e != e1 && lg[e] > l2) l2 = lg[e];
        if (l1 - l2 < TIE_THRESH) {
            int ix = atomicAdd(&g_nflag, 1);
            g_flags[ix] = n;
        }
        float t = expf(l1 - l0);
        w0 = SCALING / (1.0f + t);
        w1 = SCALING * t / (1.0f + t);
    }
    e0 = __shfl_sync(0xffffffffu, e0, 0);
    e1 = __shfl_sync(0xffffffffu, e1, 0);
    w0 = __shfl_sync(0xffffffffu, w0, 0);
    w1 = __shfl_sync(0xffffffffu, w1, 0);

#pragma unroll
    for (int c = lane; c < LSP; c += 32) {
        float val = 0.0f;
        if (c < NLOW) {
            int e = c >> 4;
            float w = (e == e0) ? w0 : ((e == e1) ? w1 : 0.0f);
            val = w * Pn[HID + c];
        }
        g_LS[(size_t)n * LSP + c] = __float2half(val);
    }
}

// ---------------------------------------------------------------------------
// k2b_a: phase A of tie repair, 4-token batched (unchanged from R14).
// ---------------------------------------------------------------------------
#define FBT 4
__global__ void __launch_bounds__(256) k2b_a(
    const float* __restrict__ x,
    const float* __restrict__ W1)
{
    __shared__ float Xs[FBT][256];
    __shared__ float Ps[8][FBT][264];
    __shared__ int toks[FBT];

    const int tid = threadIdx.x, warp = tid >> 5, lane = tid & 31;
    const int nf = g_nflag;
    const int ng = (nf + FBT - 1) / FBT;
    const int nu = ng * 8;

    for (int u = blockIdx.x; u < nu; u += gridDim.x) {
        const int gi = u >> 3, s = u & 7;

        if (tid < FBT) {
            int i = gi * FBT + tid;
            toks[tid] = (i < nf) ? g_flags[i] : -1;
        }
        __syncthreads();

        {
            int t = tid >> 6, c = tid & 63;
            int tok = toks[t];
            float4 v = make_float4(0.f, 0.f, 0.f, 0.f);
            if (tok >= 0)
                v = __ldg((const float4*)(x + (size_t)tok * DIM + s * 256 + c * 4));
            *(float4*)&Xs[t][c * 4] = v;
        }
        __syncthreads();

        float4 A0[FBT], A1[FBT];
#pragma unroll
        for (int t = 0; t < FBT; t++) {
            A0[t] = make_float4(0.f, 0.f, 0.f, 0.f);
            A1[t] = make_float4(0.f, 0.f, 0.f, 0.f);
        }
        const float* wp = W1 + (size_t)(s * 256 + warp * 32) * HID + lane * 8;

        float4 cw0[4], cw1[4], nw0[4], nw1[4];
#pragma unroll
        for (int v = 0; v < 4; v++) {
            cw0[v] = __ldg((const float4*)(wp + (size_t)v * HID));
            cw1[v] = __ldg((const float4*)(wp + (size_t)v * HID + 4));
        }
#pragma unroll
        for (int kk = 0; kk < 32; kk += 4) {
            if (kk + 4 < 32) {
#pragma unroll
                for (int v = 0; v < 4; v++) {
                    nw0[v] = __ldg((const float4*)(wp + (size_t)(kk + 4 + v) * HID));
                    nw1[v] = __ldg((const float4*)(wp + (size_t)(kk + 4 + v) * HID + 4));
                }
            }
#pragma unroll
            for (int v = 0; v < 4; v++) {
#pragma unroll
                for (int t = 0; t < FBT; t++) {
                    float xv = Xs[t][warp * 32 + kk + v];
                    A0[t].x = fmaf(xv, cw0[v].x, A0[t].x);  A0[t].y = fmaf(xv, cw0[v].y, A0[t].y);
                    A0[t].z = fmaf(xv, cw0[v].z, A0[t].z);  A0[t].w = fmaf(xv, cw0[v].w, A0[t].w);
                    A1[t].x = fmaf(xv, cw1[v].x, A1[t].x);  A1[t].y = fmaf(xv, cw1[v].y, A1[t].y);
                    A1[t].z = fmaf(xv, cw1[v].z, A1[t].z);  A1[t].w = fmaf(xv, cw1[v].w, A1[t].w);
                }
            }
#pragma unroll
            for (int v = 0; v < 4; v++) { cw0[v] = nw0[v]; cw1[v] = nw1[v]; }
        }
#pragma unroll
        for (int t = 0; t < FBT; t++) {
            *(float4*)&Ps[warp][t][lane * 8]     = A0[t];
            *(float4*)&Ps[warp][t][lane * 8 + 4] = A1[t];
        }
        __syncthreads();

#pragma unroll
        for (int t = 0; t < FBT; t++) {
            int fi = gi * FBT + t;
            if (toks[t] >= 0) {
                float h = Ps[0][t][tid];
#pragma unroll
                for (int w = 1; w < 8; w++) h += Ps[w][t][tid];
                g_Hp[((size_t)fi * 8 + s) * 256 + tid] = h;
            }
        }
        __syncthreads();
    }
}

// ---------------------------------------------------------------------------
// k2b_b: phase B — sum 8 partials per flagged token, exact logits + rewrite.
// ---------------------------------------------------------------------------
__global__ void __launch_bounds__(256) k2b_b(
    const float* __restrict__ b1,
    const float* __restrict__ W2,
    const float* __restrict__ b2)
{
    __shared__ float Hs[260];
    const int tid = threadIdx.x, warp = tid >> 5, lane = tid & 31;
    const int nf = g_nflag;

    for (int i = blockIdx.x; i < nf; i += gridDim.x) {
        const int tok = g_flags[i];
        {
            float h = 0.0f;
#pragma unroll
            for (int s = 0; s < 8; s++)
                h += g_Hp[((size_t)i * 8 + s) * 256 + tid];
            Hs[tid] = h;
        }
        __syncthreads();

        if (warp == 0) {
            float acc[NEXP];
#pragma unroll
            for (int e = 0; e < NEXP; e++) acc[e] = 0.0f;
#pragma unroll
            for (int q = 0; q < 8; q++) {
                int h = lane + 32 * q;
                float v = Hs[h] + b1[h];
                float sg = v / (1.0f + expf(-v));
#pragma unroll
                for (int e = 0; e < NEXP; e++)
                    acc[e] = fmaf(sg, W2[h * NEXP + e], acc[e]);
            }
#pragma unroll
            for (int e = 0; e < NEXP; e++)
#pragma unroll
                for (int off = 16; off > 0; off >>= 1)
                    acc[e] += __shfl_down_sync(0xffffffffu, acc[e], off);

            int e0 = 0, e1 = 0;
            float w0 = 0.0f, w1 = 0.0f;
            if (lane == 0) {
                float lg[NEXP];
#pragma unroll
                for (int e = 0; e < NEXP; e++) lg[e] = acc[e] + b2[e];
                float l0 = lg[0]; e0 = 0;
#pragma unroll
                for (int e = 1; e < NEXP; e++) if (lg[e] > l0) { l0 = lg[e]; e0 = e; }
                float l1 = -3.402823466e38f; e1 = -1;
#pragma unroll
                for (int e = 0; e < NEXP; e++) if (e != e0 && lg[e] > l1) { l1 = lg[e]; e1 = e; }
                float t = expf(l1 - l0);
                w0 = SCALING / (1.0f + t);
                w1 = SCALING * t / (1.0f + t);
            }
            e0 = __shfl_sync(0xffffffffu, e0, 0);
            e1 = __shfl_sync(0xffffffffu, e1, 0);
            w0 = __shfl_sync(0xffffffffu, w0, 0);
            w1 = __shfl_sync(0xffffffffu, w1, 0);

            const float* Pn = g_P + (size_t)tok * NCP;
#pragma unroll
            for (int c = lane; c < LSP; c += 32) {
                float val = 0.0f;
                if (c < NLOW) {
                    int e = c >> 4;
                    float w = (e == e0) ? w0 : ((e == e1) ? w1 : 0.0f);
                    val = w * Pn[HID + c];
                }
                g_LS[(size_t)tok * LSP + c] = __float2half(val);
            }
        }
        __syncthreads();
    }
}

// ---------------------------------------------------------------------------
// k3: out = base + LS @ B  (fp16 mma, K=96). BM=128 BN=128, 8 warps.
// ---------------------------------------------------------------------------
#define K3_ATILE (128 * AST)
#define K3_BTILE (32 * 136)
#define K3_SMEM (3 * K3_ATILE * 2 + 3 * K3_BTILE * 2)
__global__ void __launch_bounds__(256, 2) k3_mma(
    const float* __restrict__ base,
    float* __restrict__ out)
{
    extern __shared__ char sm[];
    __half* As = (__half*)sm;
    __half* Bsm = (__half*)(sm + 3 * K3_ATILE * 2);

    const int tid = threadIdx.x, lane = tid & 31, warp = tid >> 5;
    const int m0 = (warp & 1) * 64, n0 = (warp >> 1) * 32;
    const int row0 = blockIdx.y * 128, col0 = blockIdx.x * 128;
    const uint32_t asb = smem_u32(As), bsb = smem_u32(Bsm);

#pragma unroll
    for (int t = 0; t < 3; t++) {
#pragma unroll
        for (int q = 0; q < 2; q++) {
            int idx = tid + q * 256;
            int r = idx >> 2, c = idx & 3;
            CP_ASYNC16(asb + (uint32_t)(t * (K3_ATILE * 2) + r * (AST * 2) + c * 16),
                       g_LS + (size_t)(row0 + r) * LSP + t * 32 + c * 8);
        }
#pragma unroll
        for (int q = 0; q < 2; q++) {
            int idx = tid + q * 256;
            int k = idx >> 4, c = idx & 15;
            CP_ASYNC16(bsb + (uint32_t)(t * (K3_BTILE * 2) + k * 272 + c * 16),
                       g_Bh + (size_t)(t * 32 + k) * DIM + col0 + c * 8);
        }
        CP_COMMIT();
    }

    float acc[4][4][4];
#pragma unroll
    for (int mi = 0; mi < 4; mi++)
#pragma unroll
        for (int ni = 0; ni < 4; ni++)
#pragma unroll
            for (int q = 0; q < 4; q++) acc[mi][ni][q] = 0.0f;

#pragma unroll
    for (int t = 0; t < 3; t++) {
        if (t == 0) CP_WAIT(2);
        else if (t == 1) CP_WAIT(1);
        else CP_WAIT(0);
        __syncthreads();
        uint32_t ab = asb + (uint32_t)(t * K3_ATILE * 2);
        uint32_t bb = bsb + (uint32_t)(t * K3_BTILE * 2);
#pragma unroll
        for (int kk = 0; kk < 2; kk++) {
            uint32_t a[4][4], b[4][2];
#pragma unroll
            for (int mi = 0; mi < 4; mi++)
                ldmA(a[mi], ab + (uint32_t)((m0 + mi * 16 + (lane & 15)) * (AST * 2) +
                                            (kk * 16 + (lane >> 4) * 8) * 2));
#pragma unroll
            for (int ni = 0; ni < 4; ni++)
                ldmBT(b[ni], bb + (uint32_t)((kk * 16 + (lane & 15)) * 272 +
                                             (n0 + ni * 8) * 2));
#pragma unroll
            for (int mi = 0; mi < 4; mi++)
#pragma unroll
                for (int ni = 0; ni < 4; ni++)
                    mma16816(acc[mi][ni], a[mi], b[ni]);
        }
    }

#pragma unroll
    for (int mi = 0; mi < 4; mi++) {
        int r = row0 + m0 + mi * 16 + (lane >> 2);
#pragma unroll
        for (int ni = 0; ni < 4; ni++) {
            int c = col0 + n0 + ni * 8 + (lane & 3) * 2;
            size_t o1 = (size_t)r * DIM + c;
            size_t o2 = (size_t)(r + 8) * DIM + c;
            float2 b1v = *(const float2*)(base + o1);
            float2 b2v = *(const float2*)(base + o2);
            *(float2*)(out + o1) = make_float2(b1v.x + acc[mi][ni][0], b1v.y + acc[mi][ni][1]);
            *(float2*)(out + o2) = make_float2(b2v.x + acc[mi][ni][2], b2v.y + acc[mi][ni][3]);
        }
    }
}

// ---------------------------------------------------------------------------
extern "C" void kernel_launch(void* const* d_in, const int* in_sizes, int n_in,
                              void* d_out, int out_size)
{
    const float* x    = (const float*)d_in[0];
    const float* base = (const float*)d_in[1];
    const float* A    = (const float*)d_in[2];
    const float* B    = (const float*)d_in[3];
    const float* W1   = (const float*)d_in[4];
    const float* b1   = (const float*)d_in[5];
    const float* W2   = (const float*)d_in[6];
    const float* b2   = (const float*)d_in[7];
    float* out = (float*)d_out;

    cudaFuncSetAttribute(k3_mma, cudaFuncAttributeMaxDynamicSharedMemorySize, K3_SMEM);

    k0_all<<<16384 + 2048 + 96, 256>>>(x, W1, A, B);

    k1_mma<<<dim3(NCP / 128, NTOK / 128), 256>>>();

    k2_router<<<NTOK / 8, 256>>>(b1, W2, b2);

    // launch 3 (profiled slot): tie-repair phase A
    k2b_a<<<2048, 256>>>(x, W1);
    k2b_b<<<512, 256>>>(b1, W2, b2);

    k3_mma<<<dim3(DIM / 128, NTOK / 128), 256, K3_SMEM>>>(base, out);
}

// round 16
// speedup vs baseline: 1.0350x; 1.0350x over previous
#include <cuda_runtime.h>
#include <cuda_fp16.h>
#include <math.h>
#include <stdint.h>

#define NTOK 16384
#define DIM  2048
#define HID  256
#define NEXP 5
#define RANK 16
#define NLOW 80
#define NCP  384
#define LSP  96
#define SCALING 2.0f
#define TIE_THRESH 0.005f

#define AST  40

// ---------------- static scratch ----------------
__device__ __half g_Xh[(size_t)NTOK * DIM];
__device__ __half g_Wcat[(size_t)DIM * NCP];
__device__ __half g_Bh[(size_t)LSP * DIM];
__device__ float  g_P[(size_t)NTOK * NCP];
__device__ __half g_LS[(size_t)NTOK * LSP];
__device__ int    g_nflag;
__device__ int    g_flags[NTOK];
__device__ float  g_Hp[(size_t)NTOK * 8 * 256];   // split-K partial hidden sums

// ---------------- PTX helpers ----------------
__device__ __forceinline__ uint32_t smem_u32(const void* p) {
    uint32_t a;
    asm("{ .reg .u64 t; cvta.to.shared.u64 t, %1; cvt.u32.u64 %0, t; }" : "=r"(a) : "l"(p));
    return a;
}
#define CP_ASYNC16(sm, gm) \
    asm volatile("cp.async.cg.shared.global [%0], [%1], 16;" :: "r"((uint32_t)(sm)), "l"(gm))
#define CP_COMMIT() asm volatile("cp.async.commit_group;" ::: "memory")
#define CP_WAIT(n)  asm volatile("cp.async.wait_group %0;" :: "n"(n) : "memory")

__device__ __forceinline__ void ldmA(uint32_t* a, uint32_t addr) {
    asm volatile("ldmatrix.sync.aligned.m8n8.x4.shared.b16 {%0,%1,%2,%3}, [%4];"
        : "=r"(a[0]), "=r"(a[1]), "=r"(a[2]), "=r"(a[3]) : "r"(addr));
}
__device__ __forceinline__ void ldmBT(uint32_t* b, uint32_t addr) {
    asm volatile("ldmatrix.sync.aligned.m8n8.x2.trans.shared.b16 {%0,%1}, [%2];"
        : "=r"(b[0]), "=r"(b[1]) : "r"(addr));
}
__device__ __forceinline__ void mma16816(float* c, const uint32_t* a, const uint32_t* b) {
    asm volatile("mma.sync.aligned.m16n8k16.row.col.f32.f16.f16.f32 "
        "{%0,%1,%2,%3}, {%4,%5,%6,%7}, {%8,%9}, {%0,%1,%2,%3};"
        : "+f"(c[0]), "+f"(c[1]), "+f"(c[2]), "+f"(c[3])
        : "r"(a[0]), "r"(a[1]), "r"(a[2]), "r"(a[3]), "r"(b[0]), "r"(b[1]));
}

// ---------------------------------------------------------------------------
// k0_all: fused prep.
// ---------------------------------------------------------------------------
__global__ void k0_all(const float* __restrict__ x,
                       const float* __restrict__ W1,
                       const float* __restrict__ A,
                       const float* __restrict__ B)
{
    const int b = blockIdx.x, tid = threadIdx.x;
    if (b < 16384) {
        size_t i = ((size_t)b * 256 + tid) * 8;
        float4 a = __ldg((const float4*)(x + i));
        float4 c = __ldg((const float4*)(x + i + 4));
        __half2 h0 = __float22half2_rn(make_float2(a.x, a.y));
        __half2 h1 = __float22half2_rn(make_float2(a.z, a.w));
        __half2 h2 = __float22half2_rn(make_float2(c.x, c.y));
        __half2 h3 = __float22half2_rn(make_float2(c.z, c.w));
        *(uint4*)(g_Xh + i) = make_uint4(*(uint32_t*)&h0, *(uint32_t*)&h1,
                                         *(uint32_t*)&h2, *(uint32_t*)&h3);
        if (b == 0 && tid == 0) g_nflag = 0;
    } else if (b < 16384 + 2048) {
        int k = b - 16384;
#pragma unroll
        for (int q = 0; q < 2; q++) {
            int n = tid + q * 256;
            if (n < NCP) {
                float v = 0.0f;
                if (n < HID) v = W1[(size_t)k * HID + n];
                else if (n < HID + NLOW) {
                    int c = n - HID;
                    v = A[((size_t)(c >> 4) * DIM + k) * RANK + (c & 15)];
                }
                g_Wcat[(size_t)k * NCP + n] = __float2half(v);
            }
        }
    } else {
        int j = b - 16384 - 2048;
        for (int d = tid; d < DIM; d += 256) {
            float v = (j < NLOW) ? B[(size_t)j * DIM + d] : 0.0f;
            g_Bh[(size_t)j * DIM + d] = __float2half(v);
        }
    }
}

// ---------------------------------------------------------------------------
// k1: P = x @ Wcat  via fp16 mma.sync.  BM=128 BN=128 BK=32, 8 warps,
// 3-stage cp.async pipeline, conflict-free A tiles (stride 40 halves).
// ---------------------------------------------------------------------------
#define K1_ATILE (128 * AST)
#define K1_BTILE (32 * 136)
__global__ void __launch_bounds__(256, 2) k1_mma() {
    __shared__ alignas(16) __half As[3][K1_ATILE];
    __shared__ alignas(16) __half Bs[3][K1_BTILE];

    const int tid = threadIdx.x, lane = tid & 31, warp = tid >> 5;
    const int m0 = (warp & 1) * 64, n0 = (warp >> 1) * 32;
    const int row0 = blockIdx.y * 128, col0 = blockIdx.x * 128;

    const uint32_t asb = smem_u32(&As[0][0]);
    const uint32_t bsb = smem_u32(&Bs[0][0]);

    float acc[4][4][4];
#pragma unroll
    for (int mi = 0; mi < 4; mi++)
#pragma unroll
        for (int ni = 0; ni < 4; ni++)
#pragma unroll
            for (int q = 0; q < 4; q++) acc[mi][ni][q] = 0.0f;

    const __half* xp = g_Xh + (size_t)row0 * DIM;
    const __half* wp = g_Wcat + col0;

#define LOAD_STAGE(S, K0) do {                                                   \
    uint32_t ab = asb + (uint32_t)(S) * (K1_ATILE * 2);                          \
    uint32_t bb = bsb + (uint32_t)(S) * (K1_BTILE * 2);                          \
    _Pragma("unroll")                                                            \
    for (int q = 0; q < 2; q++) {                                                \
        int idx = tid + q * 256;                                                 \
        int r = idx >> 2, c = idx & 3;                                           \
        CP_ASYNC16(ab + (uint32_t)(r * (AST * 2) + c * 16),                      \
                   xp + (size_t)r * DIM + (K0) + c * 8);                         \
    }                                                                            \
    _Pragma("unroll")                                                            \
    for (int q = 0; q < 2; q++) {                                                \
        int idx = tid + q * 256;                                                 \
        int kr = idx >> 4, c = idx & 15;                                         \
        CP_ASYNC16(bb + (uint32_t)(kr * 272 + c * 16),                           \
                   wp + (size_t)((K0) + kr) * NCP + c * 8);                      \
    }                                                                            \
} while (0)

    LOAD_STAGE(0, 0);  CP_COMMIT();
    LOAD_STAGE(1, 32); CP_COMMIT();

    int s = 0;
    for (int i = 0; i < 64; i++) {
        CP_WAIT(1);
        __syncthreads();
        if (i + 2 < 64) {
            int sn = s + 2; if (sn >= 3) sn -= 3;
            LOAD_STAGE(sn, (i + 2) * 32);
            CP_COMMIT();
        } else {
            CP_COMMIT();
        }
        uint32_t ab = asb + (uint32_t)s * (K1_ATILE * 2);
        uint32_t bb = bsb + (uint32_t)s * (K1_BTILE * 2);
#pragma unroll
        for (int kk = 0; kk < 2; kk++) {
            uint32_t a[4][4], b[4][2];
#pragma unroll
            for (int mi = 0; mi < 4; mi++)
                ldmA(a[mi], ab + (uint32_t)((m0 + mi * 16 + (lane & 15)) * (AST * 2) +
                                            (kk * 16 + (lane >> 4) * 8) * 2));
#pragma unroll
            for (int ni = 0; ni < 4; ni++)
                ldmBT(b[ni], bb + (uint32_t)((kk * 16 + (lane & 15)) * 272 +
                                             (n0 + ni * 8) * 2));
#pragma unroll
            for (int mi = 0; mi < 4; mi++)
#pragma unroll
                for (int ni = 0; ni < 4; ni++)
                    mma16816(acc[mi][ni], a[mi], b[ni]);
        }
        if (++s >= 3) s = 0;
    }
#undef LOAD_STAGE

#pragma unroll
    for (int mi = 0; mi < 4; mi++) {
        int r = row0 + m0 + mi * 16 + (lane >> 2);
#pragma unroll
        for (int ni = 0; ni < 4; ni++) {
            int c = col0 + n0 + ni * 8 + (lane & 3) * 2;
            *(float2*)&g_P[(size_t)r * NCP + c]       = make_float2(acc[mi][ni][0], acc[mi][ni][1]);
            *(float2*)&g_P[(size_t)(r + 8) * NCP + c] = make_float2(acc[mi][ni][2], acc[mi][ni][3]);
        }
    }
}

// ---------------------------------------------------------------------------
// k2: router from P (fp32 SIMT). Flags near-tie tokens. Writes g_LS (fp16).
// (R14 version — R15 smem-staged variant regressed, reverted.)
// ---------------------------------------------------------------------------
__global__ void __launch_bounds__(256) k2_router(
    const float* __restrict__ b1,
    const float* __restrict__ W2,
    const float* __restrict__ b2)
{
    const int warp = threadIdx.x >> 5, lane = threadIdx.x & 31;
    const int n = blockIdx.x * 8 + warp;
    const float* Pn = g_P + (size_t)n * NCP;

    float acc[NEXP];
#pragma unroll
    for (int e = 0; e < NEXP; e++) acc[e] = 0.0f;
#pragma unroll
    for (int i = 0; i < 8; i++) {
        int h = lane + 32 * i;
        float v = Pn[h] + b1[h];
        float s = v / (1.0f + expf(-v));
#pragma unroll
        for (int e = 0; e < NEXP; e++)
            acc[e] = fmaf(s, W2[h * NEXP + e], acc[e]);
    }
#pragma unroll
    for (int e = 0; e < NEXP; e++)
#pragma unroll
        for (int off = 16; off > 0; off >>= 1)
            acc[e] += __shfl_down_sync(0xffffffffu, acc[e], off);

    int e0 = 0, e1 = 0;
    float w0 = 0.0f, w1 = 0.0f;
    if (lane == 0) {
        float lg[NEXP];
#pragma unroll
        for (int e = 0; e < NEXP; e++) lg[e] = acc[e] + b2[e];
        float l0 = lg[0]; e0 = 0;
#pragma unroll
        for (int e = 1; e < NEXP; e++) if (lg[e] > l0) { l0 = lg[e]; e0 = e; }
        float l1 = -3.402823466e38f; e1 = -1;
#pragma unroll
        for (int e = 0; e < NEXP; e++) if (e != e0 && lg[e] > l1) { l1 = lg[e]; e1 = e; }
        float l2 = -3.402823466e38f;
#pragma unroll
        for (int e = 0; e < NEXP; e++) if (e != e0 && e != e1 && lg[e] > l2) l2 = lg[e];
        if (l1 - l2 < TIE_THRESH) {
            int ix = atomicAdd(&g_nflag, 1);
            g_flags[ix] = n;
        }
        float t = expf(l1 - l0);
        w0 = SCALING / (1.0f + t);
        w1 = SCALING * t / (1.0f + t);
    }
    e0 = __shfl_sync(0xffffffffu, e0, 0);
    e1 = __shfl_sync(0xffffffffu, e1, 0);
    w0 = __shfl_sync(0xffffffffu, w0, 0);
    w1 = __shfl_sync(0xffffffffu, w1, 0);

#pragma unroll
    for (int c = lane; c < LSP; c += 32) {
        float val = 0.0f;
        if (c < NLOW) {
            int e = c >> 4;
            float w = (e == e0) ? w0 : ((e == e1) ? w1 : 0.0f);
            val = w * Pn[HID + c];
        }
        g_LS[(size_t)n * LSP + c] = __float2half(val);
    }
}

// ---------------------------------------------------------------------------
// k2b_a: phase A of tie repair, 8-token batched (W1 traffic /8).
// Work unit = (group of 8 flagged tokens, K-slice of 256). 8 warps x 32
// k-rows; batch-4 double-buffered W1 loads; dynamic smem for partials.
// FMA order per token identical to R14 -> bit-identical h.
// ---------------------------------------------------------------------------
#define FBT 8
#define K2BA_SMEM (8 * FBT * 264 * 4)      // Ps: 67584 B (dynamic)
__global__ void __launch_bounds__(256) k2b_a(
    const float* __restrict__ x,
    const float* __restrict__ W1)
{
    __shared__ float Xs[FBT][256];          // 8 KB static
    __shared__ int toks[FBT];
    extern __shared__ float Ps[];           // [warp][token][264]

    const int tid = threadIdx.x, warp = tid >> 5, lane = tid & 31;
    const int nf = g_nflag;
    const int ng = (nf + FBT - 1) / FBT;
    const int nu = ng * 8;

    for (int u = blockIdx.x; u < nu; u += gridDim.x) {
        const int gi = u >> 3, s = u & 7;

        if (tid < FBT) {
            int i = gi * FBT + tid;
            toks[tid] = (i < nf) ? g_flags[i] : -1;
        }
        __syncthreads();

        // stage 8 x-slices: 512 float4 over 256 threads
#pragma unroll
        for (int p = 0; p < 2; p++) {
            int idx = tid + p * 256;
            int t = idx >> 6, c = idx & 63;
            int tok = toks[t];
            float4 v = make_float4(0.f, 0.f, 0.f, 0.f);
            if (tok >= 0)
                v = __ldg((const float4*)(x + (size_t)tok * DIM + s * 256 + c * 4));
            *(float4*)&Xs[t][c * 4] = v;
        }
        __syncthreads();

        // warp's k-rows: [s*256 + warp*32, +32); lane owns hidden cols lane*8..+7
        float4 A0[FBT], A1[FBT];
#pragma unroll
        for (int t = 0; t < FBT; t++) {
            A0[t] = make_float4(0.f, 0.f, 0.f, 0.f);
            A1[t] = make_float4(0.f, 0.f, 0.f, 0.f);
        }
        const float* wp = W1 + (size_t)(s * 256 + warp * 32) * HID + lane * 8;

        float4 cw0[4], cw1[4], nw0[4], nw1[4];
#pragma unroll
        for (int v = 0; v < 4; v++) {
            cw0[v] = __ldg((const float4*)(wp + (size_t)v * HID));
            cw1[v] = __ldg((const float4*)(wp + (size_t)v * HID + 4));
        }
#pragma unroll
        for (int kk = 0; kk < 32; kk += 4) {
            if (kk + 4 < 32) {
#pragma unroll
                for (int v = 0; v < 4; v++) {
                    nw0[v] = __ldg((const float4*)(wp + (size_t)(kk + 4 + v) * HID));
                    nw1[v] = __ldg((const float4*)(wp + (size_t)(kk + 4 + v) * HID + 4));
                }
            }
#pragma unroll
            for (int v = 0; v < 4; v++) {
#pragma unroll
                for (int t = 0; t < FBT; t++) {
                    float xv = Xs[t][warp * 32 + kk + v];
                    A0[t].x = fmaf(xv, cw0[v].x, A0[t].x);  A0[t].y = fmaf(xv, cw0[v].y, A0[t].y);
                    A0[t].z = fmaf(xv, cw0[v].z, A0[t].z);  A0[t].w = fmaf(xv, cw0[v].w, A0[t].w);
                    A1[t].x = fmaf(xv, cw1[v].x, A1[t].x);  A1[t].y = fmaf(xv, cw1[v].y, A1[t].y);
                    A1[t].z = fmaf(xv, cw1[v].z, A1[t].z);  A1[t].w = fmaf(xv, cw1[v].w, A1[t].w);
                }
            }
#pragma unroll
            for (int v = 0; v < 4; v++) { cw0[v] = nw0[v]; cw1[v] = nw1[v]; }
        }
#pragma unroll
        for (int t = 0; t < FBT; t++) {
            *(float4*)&Ps[(warp * FBT + t) * 264 + lane * 8]     = A0[t];
            *(float4*)&Ps[(warp * FBT + t) * 264 + lane * 8 + 4] = A1[t];
        }
        __syncthreads();

        // reduce 8 warp-partials per token, write g_Hp
#pragma unroll
        for (int t = 0; t < FBT; t++) {
            int fi = gi * FBT + t;
            if (toks[t] >= 0) {
                float h = Ps[(0 * FBT + t) * 264 + tid];
#pragma unroll
                for (int w = 1; w < 8; w++) h += Ps[(w * FBT + t) * 264 + tid];
                g_Hp[((size_t)fi * 8 + s) * 256 + tid] = h;
            }
        }
        __syncthreads();
    }
}

// ---------------------------------------------------------------------------
// k2b_b: phase B — sum 8 partials per flagged token, exact logits + rewrite.
// ---------------------------------------------------------------------------
__global__ void __launch_bounds__(256) k2b_b(
    const float* __restrict__ b1,
    const float* __restrict__ W2,
    const float* __restrict__ b2)
{
    __shared__ float Hs[260];
    const int tid = threadIdx.x, warp = tid >> 5, lane = tid & 31;
    const int nf = g_nflag;

    for (int i = blockIdx.x; i < nf; i += gridDim.x) {
        const int tok = g_flags[i];
        {
            float h = 0.0f;
#pragma unroll
            for (int s = 0; s < 8; s++)
                h += g_Hp[((size_t)i * 8 + s) * 256 + tid];
            Hs[tid] = h;
        }
        __syncthreads();

        if (warp == 0) {
            float acc[NEXP];
#pragma unroll
            for (int e = 0; e < NEXP; e++) acc[e] = 0.0f;
#pragma unroll
            for (int q = 0; q < 8; q++) {
                int h = lane + 32 * q;
                float v = Hs[h] + b1[h];
                float sg = v / (1.0f + expf(-v));
#pragma unroll
                for (int e = 0; e < NEXP; e++)
                    acc[e] = fmaf(sg, W2[h * NEXP + e], acc[e]);
            }
#pragma unroll
            for (int e = 0; e < NEXP; e++)
#pragma unroll
                for (int off = 16; off > 0; off >>= 1)
                    acc[e] += __shfl_down_sync(0xffffffffu, acc[e], off);

            int e0 = 0, e1 = 0;
            float w0 = 0.0f, w1 = 0.0f;
            if (lane == 0) {
                float lg[NEXP];
#pragma unroll
                for (int e = 0; e < NEXP; e++) lg[e] = acc[e] + b2[e];
                float l0 = lg[0]; e0 = 0;
#pragma unroll
                for (int e = 1; e < NEXP; e++) if (lg[e] > l0) { l0 = lg[e]; e0 = e; }
                float l1 = -3.402823466e38f; e1 = -1;
#pragma unroll
                for (int e = 0; e < NEXP; e++) if (e != e0 && lg[e] > l1) { l1 = lg[e]; e1 = e; }
                float t = expf(l1 - l0);
                w0 = SCALING / (1.0f + t);
                w1 = SCALING * t / (1.0f + t);
            }
            e0 = __shfl_sync(0xffffffffu, e0, 0);
            e1 = __shfl_sync(0xffffffffu, e1, 0);
            w0 = __shfl_sync(0xffffffffu, w0, 0);
            w1 = __shfl_sync(0xffffffffu, w1, 0);

            const float* Pn = g_P + (size_t)tok * NCP;
#pragma unroll
            for (int c = lane; c < LSP; c += 32) {
                float val = 0.0f;
                if (c < NLOW) {
                    int e = c >> 4;
                    float w = (e == e0) ? w0 : ((e == e1) ? w1 : 0.0f);
                    val = w * Pn[HID + c];
                }
                g_LS[(size_t)tok * LSP + c] = __float2half(val);
            }
        }
        __syncthreads();
    }
}

// ---------------------------------------------------------------------------
// k3: out = base + LS @ B  (fp16 mma, K=96). BM=128 BN=128, 8 warps.
// ---------------------------------------------------------------------------
#define K3_ATILE (128 * AST)
#define K3_BTILE (32 * 136)
#define K3_SMEM (3 * K3_ATILE * 2 + 3 * K3_BTILE * 2)
__global__ void __launch_bounds__(256, 2) k3_mma(
    const float* __restrict__ base,
    float* __restrict__ out)
{
    extern __shared__ char sm[];
    __half* As = (__half*)sm;
    __half* Bsm = (__half*)(sm + 3 * K3_ATILE * 2);

    const int tid = threadIdx.x, lane = tid & 31, warp = tid >> 5;
    const int m0 = (warp & 1) * 64, n0 = (warp >> 1) * 32;
    const int row0 = blockIdx.y * 128, col0 = blockIdx.x * 128;
    const uint32_t asb = smem_u32(As), bsb = smem_u32(Bsm);

#pragma unroll
    for (int t = 0; t < 3; t++) {
#pragma unroll
        for (int q = 0; q < 2; q++) {
            int idx = tid + q * 256;
            int r = idx >> 2, c = idx & 3;
            CP_ASYNC16(asb + (uint32_t)(t * (K3_ATILE * 2) + r * (AST * 2) + c * 16),
                       g_LS + (size_t)(row0 + r) * LSP + t * 32 + c * 8);
        }
#pragma unroll
        for (int q = 0; q < 2; q++) {
            int idx = tid + q * 256;
            int k = idx >> 4, c = idx & 15;
            CP_ASYNC16(bsb + (uint32_t)(t * (K3_BTILE * 2) + k * 272 + c * 16),
                       g_Bh + (size_t)(t * 32 + k) * DIM + col0 + c * 8);
        }
        CP_COMMIT();
    }

    float acc[4][4][4];
#pragma unroll
    for (int mi = 0; mi < 4; mi++)
#pragma unroll
        for (int ni = 0; ni < 4; ni++)
#pragma unroll
            for (int q = 0; q < 4; q++) acc[mi][ni][q] = 0.0f;

#pragma unroll
    for (int t = 0; t < 3; t++) {
        if (t == 0) CP_WAIT(2);
        else if (t == 1) CP_WAIT(1);
        else CP_WAIT(0);
        __syncthreads();
        uint32_t ab = asb + (uint32_t)(t * K3_ATILE * 2);
        uint32_t bb = bsb + (uint32_t)(t * K3_BTILE * 2);
#pragma unroll
        for (int kk = 0; kk < 2; kk++) {
            uint32_t a[4][4], b[4][2];
#pragma unroll
            for (int mi = 0; mi < 4; mi++)
                ldmA(a[mi], ab + (uint32_t)((m0 + mi * 16 + (lane & 15)) * (AST * 2) +
                                            (kk * 16 + (lane >> 4) * 8) * 2));
#pragma unroll
            for (int ni = 0; ni < 4; ni++)
                ldmBT(b[ni], bb + (uint32_t)((kk * 16 + (lane & 15)) * 272 +
                                             (n0 + ni * 8) * 2));
#pragma unroll
            for (int mi = 0; mi < 4; mi++)
#pragma unroll
                for (int ni = 0; ni < 4; ni++)
                    mma16816(acc[mi][ni], a[mi], b[ni]);
        }
    }

#pragma unroll
    for (int mi = 0; mi < 4; mi++) {
        int r = row0 + m0 + mi * 16 + (lane >> 2);
#pragma unroll
        for (int ni = 0; ni < 4; ni++) {
            int c = col0 + n0 + ni * 8 + (lane & 3) * 2;
            size_t o1 = (size_t)r * DIM + c;
            size_t o2 = (size_t)(r + 8) * DIM + c;
            float2 b1v = *(const float2*)(base + o1);
            float2 b2v = *(const float2*)(base + o2);
            *(float2*)(out + o1) = make_float2(b1v.x + acc[mi][ni][0], b1v.y + acc[mi][ni][1]);
            *(float2*)(out + o2) = make_float2(b2v.x + acc[mi][ni][2], b2v.y + acc[mi][ni][3]);
        }
    }
}

// ---------------------------------------------------------------------------
extern "C" void kernel_launch(void* const* d_in, const int* in_sizes, int n_in,
                              void* d_out, int out_size)
{
    const float* x    = (const float*)d_in[0];
    const float* base = (const float*)d_in[1];
    const float* A    = (const float*)d_in[2];
    const float* B    = (const float*)d_in[3];
    const float* W1   = (const float*)d_in[4];
    const float* b1   = (const float*)d_in[5];
    const float* W2   = (const float*)d_in[6];
    const float* b2   = (const float*)d_in[7];
    float* out = (float*)d_out;

    cudaFuncSetAttribute(k3_mma, cudaFuncAttributeMaxDynamicSharedMemorySize, K3_SMEM);
    cudaFuncSetAttribute(k2b_a, cudaFuncAttributeMaxDynamicSharedMemorySize, K2BA_SMEM);

    k0_all<<<16384 + 2048 + 96, 256>>>(x, W1, A, B);

    k1_mma<<<dim3(NCP / 128, NTOK / 128), 256>>>();

    k2_router<<<NTOK / 8, 256>>>(b1, W2, b2);

    // launch 3 (profiled slot): 8-token batched tie-repair phase A
    k2b_a<<<2048, 256, K2BA_SMEM>>>(x, W1);
    k2b_b<<<512, 256>>>(b1, W2, b2);

    k3_mma<<<dim3(DIM / 128, NTOK / 128), 256, K3_SMEM>>>(base, out);
}